// round 4
// baseline (speedup 1.0000x reference)
#include <cuda_runtime.h>
#include <cuda_bf16.h>
#include <cstdint>

// Problem constants (GCN_60301340836134)
constexpr int N_NODES = 100000;
constexpr int N_EDGES = 1600000;
constexpr int D_IN    = 128;
constexpr int D_OUT   = 5;
constexpr int YL_PAD  = 8;   // pad y_l rows to 8 floats -> 32B = one L2 sector

// Scratch (no allocations allowed; use device globals)
__device__ float g_yl[N_NODES * YL_PAD];      // x @ W_l^T, padded
__device__ float g_agg[N_NODES * D_OUT];      // scatter accumulator
__device__ float g_deg[N_NODES];              // degree accumulator

// ---------------------------------------------------------------------------
// Kernel 0: zero agg + deg each replay (vectorized float4 stores)
// ---------------------------------------------------------------------------
__global__ void zero_kernel() {
    int i = blockIdx.x * blockDim.x + threadIdx.x;
    constexpr int AGG_F4 = (N_NODES * D_OUT) / 4;  // 125000
    constexpr int DEG_F4 = N_NODES / 4;            // 25000
    float4 z = make_float4(0.f, 0.f, 0.f, 0.f);
    if (i < AGG_F4) {
        ((float4*)g_agg)[i] = z;
    } else if (i < AGG_F4 + DEG_F4) {
        ((float4*)g_deg)[i - AGG_F4] = z;
    }
}

// ---------------------------------------------------------------------------
// Kernel 1: projection. One warp per node.
//   y_l[node] = x[node] @ W_l^T          -> g_yl (padded)
//   out[node] = x[node] @ W_r^T + b_l    -> d_out (base term)
// ---------------------------------------------------------------------------
__global__ __launch_bounds__(256) void proj_kernel(
    const float* __restrict__ x,
    const float* __restrict__ Wl,
    const float* __restrict__ bl,
    const float* __restrict__ Wr,
    float* __restrict__ out)
{
    __shared__ float4 sWl[D_OUT * (D_IN / 4)];  // 160 float4
    __shared__ float4 sWr[D_OUT * (D_IN / 4)];
    __shared__ float  sb[D_OUT];

    int tid = threadIdx.x;
    if (tid < D_OUT * (D_IN / 4)) {
        sWl[tid] = ((const float4*)Wl)[tid];
        sWr[tid] = ((const float4*)Wr)[tid];
    }
    if (tid < D_OUT) sb[tid] = bl[tid];
    __syncthreads();

    int warp = tid >> 5;
    int lane = tid & 31;
    int node = blockIdx.x * 8 + warp;
    if (node >= N_NODES) return;

    float4 xv = ((const float4*)x)[(size_t)node * (D_IN / 4) + lane];

    float acc[2 * D_OUT];
#pragma unroll
    for (int o = 0; o < D_OUT; o++) {
        float4 wl = sWl[o * (D_IN / 4) + lane];
        float4 wr = sWr[o * (D_IN / 4) + lane];
        acc[o]         = xv.x * wl.x + xv.y * wl.y + xv.z * wl.z + xv.w * wl.w;
        acc[D_OUT + o] = xv.x * wr.x + xv.y * wr.y + xv.z * wr.z + xv.w * wr.w;
    }

#pragma unroll
    for (int o = 0; o < 2 * D_OUT; o++) {
#pragma unroll
        for (int off = 16; off > 0; off >>= 1)
            acc[o] += __shfl_xor_sync(0xFFFFFFFFu, acc[o], off);
    }

    if (lane == 0) {
        float4 v0 = make_float4(acc[0], acc[1], acc[2], acc[3]);
        float4 v1 = make_float4(acc[4], 0.f, 0.f, 0.f);
        ((float4*)(g_yl + (size_t)node * YL_PAD))[0] = v0;
        ((float4*)(g_yl + (size_t)node * YL_PAD))[1] = v1;
#pragma unroll
        for (int o = 0; o < D_OUT; o++)
            out[(size_t)node * D_OUT + o] = acc[D_OUT + o] + sb[o];
    }
}

// ---------------------------------------------------------------------------
// Kernel 2: edge scatter. One thread per edge. Indices are INT32 on device
// (harness downcasts int64 inputs). Bounds-guarded so bad indices can never
// fault (they'd show up as rel_err instead).
// ---------------------------------------------------------------------------
__global__ __launch_bounds__(256) void scatter_kernel(
    const int* __restrict__ src,
    const int* __restrict__ dst)
{
    int e = blockIdx.x * blockDim.x + threadIdx.x;
    if (e >= N_EDGES) return;

    int s = src[e];
    int d = dst[e];
    if ((unsigned)s >= (unsigned)N_NODES || (unsigned)d >= (unsigned)N_NODES)
        return;

    const float4* yp = (const float4*)(g_yl + (size_t)s * YL_PAD);
    float4 a = yp[0];
    float  b = yp[1].x;

    float* ag = g_agg + (size_t)d * D_OUT;
    atomicAdd(ag + 0, a.x);
    atomicAdd(ag + 1, a.y);
    atomicAdd(ag + 2, a.z);
    atomicAdd(ag + 3, a.w);
    atomicAdd(ag + 4, b);
    atomicAdd(g_deg + d, 1.0f);
}

// ---------------------------------------------------------------------------
// Kernel 3: finalize. out[i] += agg[i] / max(deg[i], 1)
// ---------------------------------------------------------------------------
__global__ __launch_bounds__(256) void finalize_kernel(float* __restrict__ out)
{
    int i = blockIdx.x * blockDim.x + threadIdx.x;
    if (i >= N_NODES) return;

    float dg  = g_deg[i];
    float inv = 1.0f / fmaxf(dg, 1.0f);
#pragma unroll
    for (int o = 0; o < D_OUT; o++)
        out[(size_t)i * D_OUT + o] += g_agg[(size_t)i * D_OUT + o] * inv;
}

// ---------------------------------------------------------------------------
// Launch
// Inputs (metadata order): x [N*128 f32], edge_index [2*E int32 on device],
//                          W_l [5*128 f32], b_l [5 f32], W_r [5*128 f32]
// Output: [N*5 f32]
// ---------------------------------------------------------------------------
extern "C" void kernel_launch(void* const* d_in, const int* in_sizes, int n_in,
                              void* d_out, int out_size)
{
    const float* x    = (const float*)d_in[0];
    const int*   eidx = (const int*)d_in[1];
    const float* Wl   = (const float*)d_in[2];
    const float* bl   = (const float*)d_in[3];
    const float* Wr   = (const float*)d_in[4];
    float*       out  = (float*)d_out;

    const int* src = eidx;            // edge_index[0]
    const int* dst = eidx + N_EDGES;  // edge_index[1]

    {
        constexpr int TOTAL_F4 = (N_NODES * D_OUT + N_NODES) / 4; // 150000
        zero_kernel<<<(TOTAL_F4 + 255) / 256, 256>>>();
    }
    {
        int blocks = (N_NODES + 7) / 8;
        proj_kernel<<<blocks, 256>>>(x, Wl, bl, Wr, out);
    }
    {
        int blocks = (N_EDGES + 255) / 256;
        scatter_kernel<<<blocks, 256>>>(src, dst);
    }
    {
        int blocks = (N_NODES + 255) / 256;
        finalize_kernel<<<blocks, 256>>>(out);
    }
}

// round 5
// speedup vs baseline: 1.3846x; 1.3846x over previous
#include <cuda_runtime.h>
#include <cuda_bf16.h>
#include <cstdint>

// Problem constants (GCN_60301340836134)
constexpr int N_NODES = 100000;
constexpr int N_EDGES = 1600000;
constexpr int D_IN    = 128;
constexpr int D_OUT   = 5;
constexpr int YL_PAD  = 8;   // y_l rows padded to 8 floats (32B = one sector)
constexpr int AGG_PAD = 8;   // agg rows: [y0..y4, deg, pad, pad], 32B-aligned

// Scratch (no allocations allowed; use device globals)
__device__ __align__(16) float g_yl [N_NODES * YL_PAD];   // x @ W_l^T, padded
__device__ __align__(16) float g_agg[N_NODES * AGG_PAD];  // sum + deg per node

// ---------------------------------------------------------------------------
// Vector reductions (sm_90+): one L2 transaction instead of 4 / 2
// ---------------------------------------------------------------------------
__device__ __forceinline__ void red_add_v4(float* addr, float4 v) {
    asm volatile("red.global.add.v4.f32 [%0], {%1, %2, %3, %4};"
                 :: "l"(addr), "f"(v.x), "f"(v.y), "f"(v.z), "f"(v.w)
                 : "memory");
}
__device__ __forceinline__ void red_add_v2(float* addr, float a, float b) {
    asm volatile("red.global.add.v2.f32 [%0], {%1, %2};"
                 :: "l"(addr), "f"(a), "f"(b)
                 : "memory");
}

// ---------------------------------------------------------------------------
// Kernel 0: zero agg each replay (float4 stores; 800000 floats = 200000 f4)
// ---------------------------------------------------------------------------
__global__ void zero_kernel() {
    int i = blockIdx.x * blockDim.x + threadIdx.x;
    constexpr int AGG_F4 = (N_NODES * AGG_PAD) / 4;  // 200000
    if (i < AGG_F4)
        ((float4*)g_agg)[i] = make_float4(0.f, 0.f, 0.f, 0.f);
}

// ---------------------------------------------------------------------------
// Kernel 1: projection. One warp per node.
//   y_l[node] = x[node] @ W_l^T          -> g_yl (padded)
//   out[node] = x[node] @ W_r^T + b_l    -> d_out (base term)
// ---------------------------------------------------------------------------
__global__ __launch_bounds__(256) void proj_kernel(
    const float* __restrict__ x,
    const float* __restrict__ Wl,
    const float* __restrict__ bl,
    const float* __restrict__ Wr,
    float* __restrict__ out)
{
    __shared__ float4 sWl[D_OUT * (D_IN / 4)];  // 160 float4
    __shared__ float4 sWr[D_OUT * (D_IN / 4)];
    __shared__ float  sb[D_OUT];

    int tid = threadIdx.x;
    if (tid < D_OUT * (D_IN / 4)) {
        sWl[tid] = ((const float4*)Wl)[tid];
        sWr[tid] = ((const float4*)Wr)[tid];
    }
    if (tid < D_OUT) sb[tid] = bl[tid];
    __syncthreads();

    int warp = tid >> 5;
    int lane = tid & 31;
    int node = blockIdx.x * 8 + warp;
    if (node >= N_NODES) return;

    float4 xv = ((const float4*)x)[(size_t)node * (D_IN / 4) + lane];

    float acc[2 * D_OUT];
#pragma unroll
    for (int o = 0; o < D_OUT; o++) {
        float4 wl = sWl[o * (D_IN / 4) + lane];
        float4 wr = sWr[o * (D_IN / 4) + lane];
        acc[o]         = xv.x * wl.x + xv.y * wl.y + xv.z * wl.z + xv.w * wl.w;
        acc[D_OUT + o] = xv.x * wr.x + xv.y * wr.y + xv.z * wr.z + xv.w * wr.w;
    }

#pragma unroll
    for (int o = 0; o < 2 * D_OUT; o++) {
#pragma unroll
        for (int off = 16; off > 0; off >>= 1)
            acc[o] += __shfl_xor_sync(0xFFFFFFFFu, acc[o], off);
    }

    if (lane == 0) {
        ((float4*)(g_yl + (size_t)node * YL_PAD))[0] =
            make_float4(acc[0], acc[1], acc[2], acc[3]);
        ((float4*)(g_yl + (size_t)node * YL_PAD))[1] =
            make_float4(acc[4], 0.f, 0.f, 0.f);
#pragma unroll
        for (int o = 0; o < D_OUT; o++)
            out[(size_t)node * D_OUT + o] = acc[D_OUT + o] + sb[o];
    }
}

// ---------------------------------------------------------------------------
// Kernel 2: edge scatter. 4 edges per thread (int4 index loads).
//   agg[dst][0..4] += y_l[src][0..4];  agg[dst][5] += 1
// 2 vector REDs per edge instead of 6 scalar atomics.
// ---------------------------------------------------------------------------
__global__ __launch_bounds__(256) void scatter_kernel(
    const int* __restrict__ src,
    const int* __restrict__ dst)
{
    constexpr int E4 = N_EDGES / 4;  // 400000
    int t = blockIdx.x * blockDim.x + threadIdx.x;
    if (t >= E4) return;

    int4 s4 = ((const int4*)src)[t];
    int4 d4 = ((const int4*)dst)[t];

    int ss[4] = {s4.x, s4.y, s4.z, s4.w};
    int dd[4] = {d4.x, d4.y, d4.z, d4.w};

    // issue all gathers first (ILP hides L2 latency)
    float4 a[4];
    float  b[4];
#pragma unroll
    for (int k = 0; k < 4; k++) {
        unsigned s = (unsigned)ss[k];
        if (s >= (unsigned)N_NODES) s = 0;  // defensive; shouldn't happen
        const float4* yp = (const float4*)(g_yl + (size_t)s * YL_PAD);
        a[k] = yp[0];
        b[k] = yp[1].x;
    }

#pragma unroll
    for (int k = 0; k < 4; k++) {
        unsigned d = (unsigned)dd[k];
        if (d >= (unsigned)N_NODES) continue;
        float* ag = g_agg + (size_t)d * AGG_PAD;
        red_add_v4(ag, a[k]);
        red_add_v2(ag + 4, b[k], 1.0f);
    }
}

// ---------------------------------------------------------------------------
// Kernel 3: finalize. One thread per OUTPUT ELEMENT (500K threads).
//   out[n*5+o] += agg[n][o] / max(agg[n][5], 1)
// ---------------------------------------------------------------------------
__global__ __launch_bounds__(256) void finalize_kernel(float* __restrict__ out)
{
    int i = blockIdx.x * blockDim.x + threadIdx.x;
    if (i >= N_NODES * D_OUT) return;

    int n = i / D_OUT;
    int o = i - n * D_OUT;

    const float* ag = g_agg + (size_t)n * AGG_PAD;
    float dg  = ag[5];
    float inv = 1.0f / fmaxf(dg, 1.0f);
    out[i] += ag[o] * inv;
}

// ---------------------------------------------------------------------------
// Launch
// Inputs (metadata order): x [N*128 f32], edge_index [2*E int32 on device],
//                          W_l [5*128 f32], b_l [5 f32], W_r [5*128 f32]
// Output: [N*5 f32]
// ---------------------------------------------------------------------------
extern "C" void kernel_launch(void* const* d_in, const int* in_sizes, int n_in,
                              void* d_out, int out_size)
{
    const float* x    = (const float*)d_in[0];
    const int*   eidx = (const int*)d_in[1];
    const float* Wl   = (const float*)d_in[2];
    const float* bl   = (const float*)d_in[3];
    const float* Wr   = (const float*)d_in[4];
    float*       out  = (float*)d_out;

    const int* src = eidx;            // edge_index[0]
    const int* dst = eidx + N_EDGES;  // edge_index[1]

    {
        constexpr int AGG_F4 = (N_NODES * AGG_PAD) / 4; // 200000
        zero_kernel<<<(AGG_F4 + 255) / 256, 256>>>();
    }
    {
        int blocks = (N_NODES + 7) / 8;
        proj_kernel<<<blocks, 256>>>(x, Wl, bl, Wr, out);
    }
    {
        constexpr int E4 = N_EDGES / 4;
        scatter_kernel<<<(E4 + 255) / 256, 256>>>(src, dst);
    }
    {
        constexpr int TOTAL = N_NODES * D_OUT;
        finalize_kernel<<<(TOTAL + 255) / 256, 256>>>(out);
    }
}

// round 6
// speedup vs baseline: 1.3997x; 1.0109x over previous
#include <cuda_runtime.h>
#include <cuda_bf16.h>
#include <cuda_fp16.h>
#include <cstdint>

// Problem constants (GCN_60301340836134)
constexpr int N_NODES = 100000;
constexpr int N_EDGES = 1600000;
constexpr int D_IN    = 128;
constexpr int D_OUT   = 5;
constexpr int AGG_PAD = 8;   // agg rows: [y0..y4, deg, pad, pad] f32, 32B
constexpr int YL_PADH = 8;   // y_l rows: 8 fp16 = 16B = one LDG.128

// Scratch (no allocations allowed; device globals)
__device__ __align__(16) __half g_ylh [N_NODES * YL_PADH];  // x@W_l^T (fp16)
__device__ __align__(16) float  g_agg [N_NODES * AGG_PAD];  // sums + deg
__device__ __align__(16) float  g_base[N_NODES * AGG_PAD];  // x@W_r^T + b_l

// ---------------------------------------------------------------------------
// Vector reductions (sm_90+)
// ---------------------------------------------------------------------------
__device__ __forceinline__ void red_add_v4(float* addr, float4 v) {
    asm volatile("red.global.add.v4.f32 [%0], {%1, %2, %3, %4};"
                 :: "l"(addr), "f"(v.x), "f"(v.y), "f"(v.z), "f"(v.w)
                 : "memory");
}
__device__ __forceinline__ void red_add_v2(float* addr, float a, float b) {
    asm volatile("red.global.add.v2.f32 [%0], {%1, %2};"
                 :: "l"(addr), "f"(a), "f"(b)
                 : "memory");
}

// ---------------------------------------------------------------------------
// Kernel 1: projection + agg-zeroing. One warp per node, 8 nodes/block.
//   g_ylh[node]  = fp16(x[node] @ W_l^T)
//   g_base[node] = x[node] @ W_r^T + b_l
//   also zeroes g_agg (16 float4 per block; 12500 blocks * 16 = 200000)
// ---------------------------------------------------------------------------
__global__ __launch_bounds__(256) void proj_kernel(
    const float* __restrict__ x,
    const float* __restrict__ Wl,
    const float* __restrict__ bl,
    const float* __restrict__ Wr)
{
    __shared__ float4 sWl[D_OUT * (D_IN / 4)];  // 160 float4
    __shared__ float4 sWr[D_OUT * (D_IN / 4)];
    __shared__ float  sb[D_OUT];

    int tid = threadIdx.x;

    // fold in zeroing of g_agg (exactly 16 float4 per block)
    if (tid < 16) {
        int zi = blockIdx.x * 16 + tid;
        ((float4*)g_agg)[zi] = make_float4(0.f, 0.f, 0.f, 0.f);
    }

    if (tid < D_OUT * (D_IN / 4)) {
        sWl[tid] = ((const float4*)Wl)[tid];
        sWr[tid] = ((const float4*)Wr)[tid];
    }
    if (tid < D_OUT) sb[tid] = bl[tid];
    __syncthreads();

    int warp = tid >> 5;
    int lane = tid & 31;
    int node = blockIdx.x * 8 + warp;   // grid = 12500 blocks exactly

    float4 xv = ((const float4*)x)[(size_t)node * (D_IN / 4) + lane];

    float acc[2 * D_OUT];
#pragma unroll
    for (int o = 0; o < D_OUT; o++) {
        float4 wl = sWl[o * (D_IN / 4) + lane];
        float4 wr = sWr[o * (D_IN / 4) + lane];
        acc[o]         = xv.x * wl.x + xv.y * wl.y + xv.z * wl.z + xv.w * wl.w;
        acc[D_OUT + o] = xv.x * wr.x + xv.y * wr.y + xv.z * wr.z + xv.w * wr.w;
    }

#pragma unroll
    for (int o = 0; o < 2 * D_OUT; o++) {
#pragma unroll
        for (int off = 16; off > 0; off >>= 1)
            acc[o] += __shfl_xor_sync(0xFFFFFFFFu, acc[o], off);
    }

    if (lane == 0) {
        // pack y_l (5 values) into 8 fp16 = one 16B row
        __half2 h01 = __floats2half2_rn(acc[0], acc[1]);
        __half2 h23 = __floats2half2_rn(acc[2], acc[3]);
        __half2 h4z = __floats2half2_rn(acc[4], 0.f);
        uint4 u;
        u.x = *(unsigned*)&h01;
        u.y = *(unsigned*)&h23;
        u.z = *(unsigned*)&h4z;
        u.w = 0u;
        ((uint4*)(g_ylh + (size_t)node * YL_PADH))[0] = u;

        // base term (f32, padded row)
        float4* bp = (float4*)(g_base + (size_t)node * AGG_PAD);
        bp[0] = make_float4(acc[5] + sb[0], acc[6] + sb[1],
                            acc[7] + sb[2], acc[8] + sb[3]);
        bp[1] = make_float4(acc[9] + sb[4], 0.f, 0.f, 0.f);
    }
}

// ---------------------------------------------------------------------------
// Kernel 2: edge scatter. 4 edges per thread (int4 index loads).
// Per edge: ONE 16B gather (8 fp16) + v4.f32 RED + v2.f32 RED.
// ---------------------------------------------------------------------------
__global__ __launch_bounds__(256) void scatter_kernel(
    const int* __restrict__ src,
    const int* __restrict__ dst)
{
    constexpr int E4 = N_EDGES / 4;  // 400000
    int t = blockIdx.x * blockDim.x + threadIdx.x;
    if (t >= E4) return;

    int4 s4 = ((const int4*)src)[t];
    int4 d4 = ((const int4*)dst)[t];

    int ss[4] = {s4.x, s4.y, s4.z, s4.w};
    int dd[4] = {d4.x, d4.y, d4.z, d4.w};

    // batch the gathers (MLP hides L2 latency)
    uint4 u[4];
#pragma unroll
    for (int k = 0; k < 4; k++) {
        unsigned s = (unsigned)ss[k];
        if (s >= (unsigned)N_NODES) s = 0;  // defensive
        u[k] = ((const uint4*)(g_ylh + (size_t)s * YL_PADH))[0];
    }

#pragma unroll
    for (int k = 0; k < 4; k++) {
        unsigned d = (unsigned)dd[k];
        if (d >= (unsigned)N_NODES) continue;

        __half2 h01 = *(__half2*)&u[k].x;
        __half2 h23 = *(__half2*)&u[k].y;
        __half2 h4z = *(__half2*)&u[k].z;
        float2 f01 = __half22float2(h01);
        float2 f23 = __half22float2(h23);
        float  f4  = __low2float(h4z);

        float* ag = g_agg + (size_t)d * AGG_PAD;
        red_add_v4(ag, make_float4(f01.x, f01.y, f23.x, f23.y));
        red_add_v2(ag + 4, f4, 1.0f);
    }
}

// ---------------------------------------------------------------------------
// Kernel 3: finalize, fully coalesced.
//   out[n][o] = base[n][o] + agg[n][o] / max(deg, 1)
// One thread per node; smem-staged so out is written as float4s.
// ---------------------------------------------------------------------------
__global__ __launch_bounds__(256) void finalize_kernel(float* __restrict__ out)
{
    __shared__ float s_out[256 * D_OUT];  // 1280 floats = 320 float4

    int tid  = threadIdx.x;
    int node = blockIdx.x * 256 + tid;

    if (node < N_NODES) {
        const float4* ap = (const float4*)(g_agg  + (size_t)node * AGG_PAD);
        const float4* bp = (const float4*)(g_base + (size_t)node * AGG_PAD);
        float4 a0 = ap[0], a1 = ap[1];
        float4 b0 = bp[0], b1 = bp[1];

        float inv = 1.0f / fmaxf(a1.y, 1.0f);   // deg in lane 5

        s_out[tid * D_OUT + 0] = b0.x + a0.x * inv;
        s_out[tid * D_OUT + 1] = b0.y + a0.y * inv;
        s_out[tid * D_OUT + 2] = b0.z + a0.z * inv;
        s_out[tid * D_OUT + 3] = b0.w + a0.w * inv;
        s_out[tid * D_OUT + 4] = b1.x + a1.x * inv;
    }
    __syncthreads();

    // coalesced float4 stores: block covers out[block*1280 .. +1280)
    int base_f  = blockIdx.x * 256 * D_OUT;
    int total_f = N_NODES * D_OUT;
#pragma unroll
    for (int j = tid; j < 320; j += 256) {
        int f = base_f + j * 4;
        if (f + 3 < total_f) {
            ((float4*)out)[base_f / 4 + j] = ((const float4*)s_out)[j];
        } else if (f < total_f) {
            for (int q = 0; q < total_f - f; q++)
                out[f + q] = s_out[j * 4 + q];
        }
    }
}

// ---------------------------------------------------------------------------
// Launch
// Inputs (metadata order): x [N*128 f32], edge_index [2*E int32 on device],
//                          W_l [5*128 f32], b_l [5 f32], W_r [5*128 f32]
// Output: [N*5 f32]
// ---------------------------------------------------------------------------
extern "C" void kernel_launch(void* const* d_in, const int* in_sizes, int n_in,
                              void* d_out, int out_size)
{
    const float* x    = (const float*)d_in[0];
    const int*   eidx = (const int*)d_in[1];
    const float* Wl   = (const float*)d_in[2];
    const float* bl   = (const float*)d_in[3];
    const float* Wr   = (const float*)d_in[4];
    float*       out  = (float*)d_out;

    const int* src = eidx;            // edge_index[0]
    const int* dst = eidx + N_EDGES;  // edge_index[1]

    {
        int blocks = N_NODES / 8;     // 12500 exactly; also zeroes g_agg
        proj_kernel<<<blocks, 256>>>(x, Wl, bl, Wr);
    }
    {
        constexpr int E4 = N_EDGES / 4;
        scatter_kernel<<<(E4 + 255) / 256, 256>>>(src, dst);
    }
    {
        int blocks = (N_NODES + 255) / 256;
        finalize_kernel<<<blocks, 256>>>(out);
    }
}

// round 7
// speedup vs baseline: 2.2649x; 1.6181x over previous
#include <cuda_runtime.h>
#include <cuda_bf16.h>
#include <cuda_fp16.h>
#include <cstdint>

// Problem constants (GCN_60301340836134)
constexpr int N_NODES = 100000;
constexpr int N_EDGES = 1600000;
constexpr int D_IN    = 128;
constexpr int D_OUT   = 5;
constexpr int NOUT2   = 2 * D_OUT;          // 10 fused outputs (W_l | W_r)
constexpr int AGG_PAD = 8;                  // f32 rows: [y0..y4, deg, pad, pad]
constexpr int YL_PADH = 8;                  // fp16 rows: 16B = one LDG.128

constexpr int NPB     = 256;                // nodes per block (= threads)
constexpr int K4      = D_IN / 4;           // 32 float4 per x row
constexpr int KT4     = 8;                  // float4 per k-tile
constexpr int NTILES  = K4 / KT4;           // 4
constexpr int XROW    = 9;                  // smem row stride in float4 (36 floats)

// Scratch (no allocations allowed; device globals)
__device__ __align__(16) __half g_ylh [N_NODES * YL_PADH];  // x@W_l^T (fp16)
__device__ __align__(16) float  g_agg [N_NODES * AGG_PAD];  // sums + deg
__device__ __align__(16) float  g_base[N_NODES * AGG_PAD];  // x@W_r^T + b_l

// ---------------------------------------------------------------------------
// Vector reductions (sm_90+)
// ---------------------------------------------------------------------------
__device__ __forceinline__ void red_add_v4(float* addr, float4 v) {
    asm volatile("red.global.add.v4.f32 [%0], {%1, %2, %3, %4};"
                 :: "l"(addr), "f"(v.x), "f"(v.y), "f"(v.z), "f"(v.w)
                 : "memory");
}
__device__ __forceinline__ void red_add_v2(float* addr, float a, float b) {
    asm volatile("red.global.add.v2.f32 [%0], {%1, %2};"
                 :: "l"(addr), "f"(a), "f"(b)
                 : "memory");
}

// ---------------------------------------------------------------------------
// Kernel 1: projection (thread-per-node, smem-staged x) + agg zeroing.
//   g_ylh[node]  = fp16(x[node] @ W_l^T)
//   g_base[node] = x[node] @ W_r^T + b_l
// ---------------------------------------------------------------------------
__global__ __launch_bounds__(NPB) void proj_kernel(
    const float* __restrict__ x,
    const float* __restrict__ Wl,
    const float* __restrict__ bl,
    const float* __restrict__ Wr)
{
    __shared__ float4 sx[NPB * XROW];        // 256 rows x 36 floats = 36.9 KB
    __shared__ float4 sW[K4 * NOUT2];        // [k4][o] packed, 5.1 KB
    __shared__ float  sb[D_OUT];

    const int tid = threadIdx.x;
    const int blockBase = blockIdx.x * NPB;

    // fold in zeroing of g_agg: 512 float4 per block, 391 blocks covers 200000
    {
        constexpr int AGG_F4 = (N_NODES * AGG_PAD) / 4;  // 200000
        float4 z = make_float4(0.f, 0.f, 0.f, 0.f);
#pragma unroll
        for (int j = 0; j < 2; j++) {
            int zi = blockIdx.x * 512 + j * NPB + tid;
            if (zi < AGG_F4) ((float4*)g_agg)[zi] = z;
        }
    }

    // weights: sW[k4*10 + o] = float4 of W[o][4*k4 .. 4*k4+3]; o<5 -> Wl, else Wr
    for (int i = tid; i < K4 * NOUT2; i += NPB) {
        int k4 = i / NOUT2;
        int o  = i - k4 * NOUT2;
        sW[i] = (o < D_OUT) ? ((const float4*)Wl)[o * K4 + k4]
                            : ((const float4*)Wr)[(o - D_OUT) * K4 + k4];
    }
    if (tid < D_OUT) sb[tid] = bl[tid];

    float acc[NOUT2];
#pragma unroll
    for (int o = 0; o < NOUT2; o++) acc[o] = 0.f;

    const float4* x4 = (const float4*)x;

#pragma unroll
    for (int t = 0; t < NTILES; t++) {
        __syncthreads();   // also covers the weight/bias staging before tile 0
        // cooperative coalesced load of x[:, tile] into smem
#pragma unroll
        for (int j = 0; j < KT4; j++) {
            int idx = j * NPB + tid;           // 0..2047
            int n   = idx >> 3;                // node-in-block
            int c   = idx & 7;                 // chunk-in-tile
            int node = blockBase + n;
            float4 v = (node < N_NODES)
                         ? x4[(size_t)node * K4 + t * KT4 + c]
                         : make_float4(0.f, 0.f, 0.f, 0.f);
            sx[n * XROW + c] = v;
        }
        __syncthreads();

        // each thread: its own row, 8 float4 x 10 outputs
#pragma unroll
        for (int c = 0; c < KT4; c++) {
            float4 xv = sx[tid * XROW + c];
            int kb = (t * KT4 + c) * NOUT2;
#pragma unroll
            for (int o = 0; o < NOUT2; o++) {
                float4 w = sW[kb + o];
                acc[o] += xv.x * w.x + xv.y * w.y + xv.z * w.z + xv.w * w.w;
            }
        }
    }

    int node = blockBase + tid;
    if (node < N_NODES) {
        // fp16-packed y_l row (one 16B store)
        __half2 h01 = __floats2half2_rn(acc[0], acc[1]);
        __half2 h23 = __floats2half2_rn(acc[2], acc[3]);
        __half2 h4z = __floats2half2_rn(acc[4], 0.f);
        uint4 u;
        u.x = *(unsigned*)&h01;
        u.y = *(unsigned*)&h23;
        u.z = *(unsigned*)&h4z;
        u.w = 0u;
        ((uint4*)(g_ylh + (size_t)node * YL_PADH))[0] = u;

        // base term (f32, padded row)
        float4* bp = (float4*)(g_base + (size_t)node * AGG_PAD);
        bp[0] = make_float4(acc[5] + sb[0], acc[6] + sb[1],
                            acc[7] + sb[2], acc[8] + sb[3]);
        bp[1] = make_float4(acc[9] + sb[4], 0.f, 0.f, 0.f);
    }
}

// ---------------------------------------------------------------------------
// Kernel 2: edge scatter. 4 edges per thread (int4 index loads).
// Per edge: ONE 16B gather (8 fp16) + v4.f32 RED + v2.f32 RED.
// ---------------------------------------------------------------------------
__global__ __launch_bounds__(256) void scatter_kernel(
    const int* __restrict__ src,
    const int* __restrict__ dst)
{
    constexpr int E4 = N_EDGES / 4;  // 400000
    int t = blockIdx.x * blockDim.x + threadIdx.x;
    if (t >= E4) return;

    int4 s4 = ((const int4*)src)[t];
    int4 d4 = ((const int4*)dst)[t];

    int ss[4] = {s4.x, s4.y, s4.z, s4.w};
    int dd[4] = {d4.x, d4.y, d4.z, d4.w};

    uint4 u[4];
#pragma unroll
    for (int k = 0; k < 4; k++) {
        unsigned s = (unsigned)ss[k];
        if (s >= (unsigned)N_NODES) s = 0;  // defensive
        u[k] = ((const uint4*)(g_ylh + (size_t)s * YL_PADH))[0];
    }

#pragma unroll
    for (int k = 0; k < 4; k++) {
        unsigned d = (unsigned)dd[k];
        if (d >= (unsigned)N_NODES) continue;

        __half2 h01 = *(__half2*)&u[k].x;
        __half2 h23 = *(__half2*)&u[k].y;
        __half2 h4z = *(__half2*)&u[k].z;
        float2 f01 = __half22float2(h01);
        float2 f23 = __half22float2(h23);
        float  f4  = __low2float(h4z);

        float* ag = g_agg + (size_t)d * AGG_PAD;
        red_add_v4(ag, make_float4(f01.x, f01.y, f23.x, f23.y));
        red_add_v2(ag + 4, f4, 1.0f);
    }
}

// ---------------------------------------------------------------------------
// Kernel 3: finalize, fully coalesced.
//   out[n][o] = base[n][o] + agg[n][o] / max(deg, 1)
// ---------------------------------------------------------------------------
__global__ __launch_bounds__(256) void finalize_kernel(float* __restrict__ out)
{
    __shared__ float s_out[256 * D_OUT];  // 1280 floats = 320 float4

    int tid  = threadIdx.x;
    int node = blockIdx.x * 256 + tid;

    if (node < N_NODES) {
        const float4* ap = (const float4*)(g_agg  + (size_t)node * AGG_PAD);
        const float4* bp = (const float4*)(g_base + (size_t)node * AGG_PAD);
        float4 a0 = ap[0], a1 = ap[1];
        float4 b0 = bp[0], b1 = bp[1];

        float inv = 1.0f / fmaxf(a1.y, 1.0f);   // deg in lane 5

        s_out[tid * D_OUT + 0] = b0.x + a0.x * inv;
        s_out[tid * D_OUT + 1] = b0.y + a0.y * inv;
        s_out[tid * D_OUT + 2] = b0.z + a0.z * inv;
        s_out[tid * D_OUT + 3] = b0.w + a0.w * inv;
        s_out[tid * D_OUT + 4] = b1.x + a1.x * inv;
    }
    __syncthreads();

    int base_f  = blockIdx.x * 256 * D_OUT;
    int total_f = N_NODES * D_OUT;
#pragma unroll
    for (int j = tid; j < 320; j += 256) {
        int f = base_f + j * 4;
        if (f + 3 < total_f) {
            ((float4*)out)[base_f / 4 + j] = ((const float4*)s_out)[j];
        } else if (f < total_f) {
            for (int q = 0; q < total_f - f; q++)
                out[f + q] = s_out[j * 4 + q];
        }
    }
}

// ---------------------------------------------------------------------------
// Launch
// Inputs (metadata order): x [N*128 f32], edge_index [2*E int32 on device],
//                          W_l [5*128 f32], b_l [5 f32], W_r [5*128 f32]
// Output: [N*5 f32]
// ---------------------------------------------------------------------------
extern "C" void kernel_launch(void* const* d_in, const int* in_sizes, int n_in,
                              void* d_out, int out_size)
{
    const float* x    = (const float*)d_in[0];
    const int*   eidx = (const int*)d_in[1];
    const float* Wl   = (const float*)d_in[2];
    const float* bl   = (const float*)d_in[3];
    const float* Wr   = (const float*)d_in[4];
    float*       out  = (float*)d_out;

    const int* src = eidx;            // edge_index[0]
    const int* dst = eidx + N_EDGES;  // edge_index[1]

    {
        int blocks = (N_NODES + NPB - 1) / NPB;   // 391; also zeroes g_agg
        proj_kernel<<<blocks, NPB>>>(x, Wl, bl, Wr);
    }
    {
        constexpr int E4 = N_EDGES / 4;
        scatter_kernel<<<(E4 + 255) / 256, 256>>>(src, dst);
    }
    {
        int blocks = (N_NODES + 255) / 256;
        finalize_kernel<<<blocks, 256>>>(out);
    }
}